// round 1
// baseline (speedup 1.0000x reference)
#include <cuda_runtime.h>
#include <cuda_bf16.h>

#define BATCH 8
#define NDIM 256      // DIM
#define NHEADS 8
#define DHEAD 64
#define HID 512       // NHEADS*DHEAD
#define NPIX 4096     // 64*64
#define M1 1536       // 3*HID

// ---------------- scratch (device globals; no allocation allowed) ----------
__device__ float g_q[(size_t)BATCH * HID * NPIX];
__device__ float g_k[(size_t)BATCH * HID * NPIX];
__device__ float g_v[(size_t)BATCH * HID * NPIX];
__device__ float g_o[(size_t)BATCH * HID * NPIX];
__device__ float g_kv[(size_t)BATCH * NHEADS * DHEAD * DHEAD];   // [pair][d][e]
__device__ float g_ksum[(size_t)BATCH * NHEADS * DHEAD];

// ---------------- K0: zero the kv/ksum accumulators ------------------------
__global__ void zero_acc_kernel() {
    int i = blockIdx.x * blockDim.x + threadIdx.x;
    const int NKV = BATCH * NHEADS * DHEAD * DHEAD;   // 262144
    const int NKS = BATCH * NHEADS * DHEAD;           // 4096
    if (i < NKV) g_kv[i] = 0.0f;
    if (i < NKS) g_ksum[i] = 0.0f;
}

// ---------------- K1: qkv = Wqkv @ x, fused elu1 + contact scaling ---------
// A = Wqkv [1536,256] row-major; B = x[b] [256,4096] row-major.
// 128x128 block tile, BK=8, 8x8 per thread, 256 threads.
__global__ __launch_bounds__(256) void qkv_gemm_kernel(
    const float* __restrict__ x, const float* __restrict__ Wqkv,
    const float* __restrict__ cm, const float* __restrict__ csp)
{
    const int b     = blockIdx.z;
    const int mBase = blockIdx.y * 128;
    const int nBase = blockIdx.x * 128;
    const float* A  = Wqkv;
    const float* Bm = x + (size_t)b * NDIM * NPIX;

    __shared__ float As[8][128];
    __shared__ float Bs[8][128];

    const int tid = threadIdx.x;
    const int tx = tid & 15, ty = tid >> 4;

    float acc[8][8];
    #pragma unroll
    for (int i = 0; i < 8; i++)
        #pragma unroll
        for (int j = 0; j < 8; j++) acc[i][j] = 0.0f;

    const int aRow = tid >> 1;          // 0..127
    const int aK4  = (tid & 1) * 4;     // 0 or 4
    const int bRow = tid >> 5;          // 0..7
    const int bC4  = (tid & 31) * 4;    // 0..124

    for (int k0 = 0; k0 < NDIM; k0 += 8) {
        float4 av = *(const float4*)&A[(size_t)(mBase + aRow) * NDIM + k0 + aK4];
        As[aK4 + 0][aRow] = av.x;
        As[aK4 + 1][aRow] = av.y;
        As[aK4 + 2][aRow] = av.z;
        As[aK4 + 3][aRow] = av.w;
        *(float4*)&Bs[bRow][bC4] =
            *(const float4*)&Bm[(size_t)(k0 + bRow) * NPIX + nBase + bC4];
        __syncthreads();
        #pragma unroll
        for (int k = 0; k < 8; k++) {
            float ar[8], br[8];
            #pragma unroll
            for (int i = 0; i < 8; i++) ar[i] = As[k][ty * 8 + i];
            #pragma unroll
            for (int j = 0; j < 8; j++) br[j] = Bs[k][tx * 8 + j];
            #pragma unroll
            for (int i = 0; i < 8; i++)
                #pragma unroll
                for (int j = 0; j < 8; j++) acc[i][j] += ar[i] * br[j];
        }
        __syncthreads();
    }

    // Epilogue: rows [row0,row0+7] all fall in one group (aligned by 8 < 512).
    const int row0 = mBase + ty * 8;
    const int col0 = nBase + tx * 8;
    const int grp  = row0 / HID;        // 0=q, 1=k, 2=v
    const int idx0 = row0 % HID;

    float cmv[8];
    if (grp == 1) {
        const float cs = *csp;
        #pragma unroll
        for (int j = 0; j < 8; j++)
            cmv[j] = 1.0f + cs * cm[(size_t)b * NPIX + col0 + j];
    }
    float* dst = (grp == 0) ? g_q : (grp == 1) ? g_k : g_v;

    #pragma unroll
    for (int i = 0; i < 8; i++) {
        float* drow = dst + ((size_t)b * HID + idx0 + i) * NPIX + col0;
        #pragma unroll
        for (int j = 0; j < 8; j++) {
            float v = acc[i][j];
            if (grp < 2) v = (v > 0.0f) ? (v + 1.0f) : __expf(v);
            if (grp == 1) v *= cmv[j];
            drow[j] = v;
        }
    }
}

// ---------------- K2: kv[d][e] += sum_n k[d][n]*v[e][n]; ksum[d] += sum k ---
// grid: (8 n-chunks of 512, 64 (b,h) pairs); 256 threads; 4x4 per thread.
__global__ __launch_bounds__(256) void kv_reduce_kernel()
{
    const int pair = blockIdx.y;              // b*8 + h
    const int b = pair >> 3, h = pair & 7;
    const int n0 = blockIdx.x * 512;
    const float* kp = g_k + ((size_t)b * HID + h * DHEAD) * NPIX;
    const float* vp = g_v + ((size_t)b * HID + h * DHEAD) * NPIX;

    __shared__ float ks[64][33];
    __shared__ float vs[64][33];

    const int tid = threadIdx.x;
    const int tx = tid & 15, ty = tid >> 4;

    float acc[4][4];
    #pragma unroll
    for (int i = 0; i < 4; i++)
        #pragma unroll
        for (int j = 0; j < 4; j++) acc[i][j] = 0.0f;
    float ksum = 0.0f;

    for (int kt = 0; kt < 512; kt += 32) {
        #pragma unroll
        for (int r = 0; r < 2; r++) {
            int li  = tid + r * 256;          // 0..511
            int row = li >> 3;                // 0..63
            int c4  = (li & 7) * 4;           // 0..28
            float4 kd = *(const float4*)&kp[(size_t)row * NPIX + n0 + kt + c4];
            ks[row][c4 + 0] = kd.x; ks[row][c4 + 1] = kd.y;
            ks[row][c4 + 2] = kd.z; ks[row][c4 + 3] = kd.w;
            float4 vd = *(const float4*)&vp[(size_t)row * NPIX + n0 + kt + c4];
            vs[row][c4 + 0] = vd.x; vs[row][c4 + 1] = vd.y;
            vs[row][c4 + 2] = vd.z; vs[row][c4 + 3] = vd.w;
        }
        __syncthreads();
        if (tid < 64) {
            #pragma unroll
            for (int c = 0; c < 32; c++) ksum += ks[tid][c];
        }
        #pragma unroll
        for (int c = 0; c < 32; c++) {
            float a[4], bb[4];
            #pragma unroll
            for (int i = 0; i < 4; i++) a[i] = ks[ty * 4 + i][c];
            #pragma unroll
            for (int j = 0; j < 4; j++) bb[j] = vs[tx * 4 + j][c];
            #pragma unroll
            for (int i = 0; i < 4; i++)
                #pragma unroll
                for (int j = 0; j < 4; j++) acc[i][j] += a[i] * bb[j];
        }
        __syncthreads();
    }

    float* kvp = g_kv + (size_t)pair * DHEAD * DHEAD;
    #pragma unroll
    for (int i = 0; i < 4; i++)
        #pragma unroll
        for (int j = 0; j < 4; j++)
            atomicAdd(&kvp[(ty * 4 + i) * DHEAD + tx * 4 + j], acc[i][j]);
    if (tid < 64) atomicAdd(&g_ksum[(size_t)pair * DHEAD + tid], ksum);
}

// ---------------- K3: out[h*64+e][n] = z * sum_d kv[d][e]*q[d][n] ----------
// grid: (16 n-tiles of 256, 64 pairs); 256 threads; one n-column per thread.
__global__ __launch_bounds__(256) void attn_out_kernel()
{
    const int pair = blockIdx.y;
    const int b = pair >> 3, h = pair & 7;
    const int n = blockIdx.x * 256 + threadIdx.x;
    const int tid = threadIdx.x;

    __shared__ float kvs[64][65];
    __shared__ float ksums[64];

    const float* kvp = g_kv + (size_t)pair * 4096;
    for (int i = tid; i < 4096; i += 256) kvs[i >> 6][i & 63] = kvp[i];
    if (tid < 64) ksums[tid] = g_ksum[(size_t)pair * 64 + tid];
    __syncthreads();

    const float* qp = g_q + ((size_t)b * HID + h * DHEAD) * NPIX + n;
    float qreg[64];
    float denom = 1e-6f;
    #pragma unroll
    for (int d = 0; d < 64; d++) {
        qreg[d] = qp[(size_t)d * NPIX];
        denom += qreg[d] * ksums[d];
    }
    const float z = 1.0f / denom;

    float* op = g_o + ((size_t)b * HID + h * DHEAD) * NPIX + n;
    #pragma unroll
    for (int et = 0; et < 4; et++) {
        float acc[16];
        #pragma unroll
        for (int e = 0; e < 16; e++) acc[e] = 0.0f;
        #pragma unroll
        for (int d = 0; d < 64; d++) {
            float qd = qreg[d];
            #pragma unroll
            for (int e = 0; e < 16; e++) acc[e] += kvs[d][et * 16 + e] * qd;
        }
        #pragma unroll
        for (int e = 0; e < 16; e++)
            op[(size_t)(et * 16 + e) * NPIX] = acc[e] * z;
    }
}

// ---------------- K4: y = Wout @ out + bout --------------------------------
// A = Wout [256,512]; B = g_o[b] [512,4096]. Same tiling as K1.
__global__ __launch_bounds__(256) void out_gemm_kernel(
    const float* __restrict__ Wout, const float* __restrict__ bout,
    float* __restrict__ y)
{
    const int b     = blockIdx.z;
    const int mBase = blockIdx.y * 128;
    const int nBase = blockIdx.x * 128;
    const float* A  = Wout;
    const float* Bm = g_o + (size_t)b * HID * NPIX;

    __shared__ float As[8][128];
    __shared__ float Bs[8][128];

    const int tid = threadIdx.x;
    const int tx = tid & 15, ty = tid >> 4;

    float acc[8][8];
    #pragma unroll
    for (int i = 0; i < 8; i++)
        #pragma unroll
        for (int j = 0; j < 8; j++) acc[i][j] = 0.0f;

    const int aRow = tid >> 1;
    const int aK4  = (tid & 1) * 4;
    const int bRow = tid >> 5;
    const int bC4  = (tid & 31) * 4;

    for (int k0 = 0; k0 < HID; k0 += 8) {
        float4 av = *(const float4*)&A[(size_t)(mBase + aRow) * HID + k0 + aK4];
        As[aK4 + 0][aRow] = av.x;
        As[aK4 + 1][aRow] = av.y;
        As[aK4 + 2][aRow] = av.z;
        As[aK4 + 3][aRow] = av.w;
        *(float4*)&Bs[bRow][bC4] =
            *(const float4*)&Bm[(size_t)(k0 + bRow) * NPIX + nBase + bC4];
        __syncthreads();
        #pragma unroll
        for (int k = 0; k < 8; k++) {
            float ar[8], br[8];
            #pragma unroll
            for (int i = 0; i < 8; i++) ar[i] = As[k][ty * 8 + i];
            #pragma unroll
            for (int j = 0; j < 8; j++) br[j] = Bs[k][tx * 8 + j];
            #pragma unroll
            for (int i = 0; i < 8; i++)
                #pragma unroll
                for (int j = 0; j < 8; j++) acc[i][j] += ar[i] * br[j];
        }
        __syncthreads();
    }

    const int row0 = mBase + ty * 8;
    const int col0 = nBase + tx * 8;
    #pragma unroll
    for (int i = 0; i < 8; i++) {
        const float bias = bout[row0 + i];
        float* drow = y + ((size_t)b * NDIM + row0 + i) * NPIX + col0;
        #pragma unroll
        for (int j = 0; j < 8; j++) drow[j] = acc[i][j] + bias;
    }
}

// ---------------- launch ----------------------------------------------------
extern "C" void kernel_launch(void* const* d_in, const int* in_sizes, int n_in,
                              void* d_out, int out_size)
{
    const float* x    = (const float*)d_in[0];  // [8,256,64,64]
    const float* cm   = (const float*)d_in[1];  // [8,1,64,64]
    const float* Wqkv = (const float*)d_in[2];  // [1536,256]
    const float* Wout = (const float*)d_in[3];  // [256,512]
    const float* bout = (const float*)d_in[4];  // [256]
    const float* cs   = (const float*)d_in[5];  // scalar
    float* y = (float*)d_out;                   // [8,256,64,64]

    // K0: zero accumulators (262144 + 4096 elements)
    zero_acc_kernel<<<(BATCH * NHEADS * DHEAD * DHEAD + 255) / 256, 256>>>();

    // K1: qkv projection + elu1 + contact scaling
    {
        dim3 grid(NPIX / 128, M1 / 128, BATCH);   // 32 x 12 x 8
        qkv_gemm_kernel<<<grid, 256>>>(x, Wqkv, cm, cs);
    }

    // K2: kv outer-product reduction + ksum
    {
        dim3 grid(NPIX / 512, BATCH * NHEADS);    // 8 x 64
        kv_reduce_kernel<<<grid, 256>>>();
    }

    // K3: normalized attention output
    {
        dim3 grid(NPIX / 256, BATCH * NHEADS);    // 16 x 64
        attn_out_kernel<<<grid, 256>>>();
    }

    // K4: output projection + bias
    {
        dim3 grid(NPIX / 128, NDIM / 128, BATCH); // 32 x 2 x 8
        out_gemm_kernel<<<grid, 256>>>(Wout, bout, y);
    }
}

// round 2
// speedup vs baseline: 1.9176x; 1.9176x over previous
#include <cuda_runtime.h>
#include <cuda_bf16.h>
#include <cstdint>

#define BATCH 8
#define NDIM 256      // DIM
#define NHEADS 8
#define DHEAD 64
#define HID 512       // NHEADS*DHEAD
#define NPIX 4096     // 64*64
#define M1 1536       // 3*HID

// ---------------- scratch (device globals; no allocation allowed) ----------
__device__ float g_q[(size_t)BATCH * HID * NPIX];
__device__ float g_k[(size_t)BATCH * HID * NPIX];
__device__ float g_v[(size_t)BATCH * HID * NPIX];
__device__ float g_o[(size_t)BATCH * HID * NPIX];
__device__ float g_kv[(size_t)BATCH * NHEADS * DHEAD * DHEAD];   // [pair][d][e]
__device__ float g_ksum[(size_t)BATCH * NHEADS * DHEAD];

// ---------------- helpers ---------------------------------------------------
__device__ __forceinline__ uint32_t f2tf32(float x) {
    uint32_t r;
    asm("cvt.rna.tf32.f32 %0, %1;" : "=r"(r) : "f"(x));
    return r;
}

__device__ __forceinline__ void mma_tf32(float c[4],
                                         uint32_t a0, uint32_t a1, uint32_t a2, uint32_t a3,
                                         uint32_t b0, uint32_t b1) {
    asm volatile(
        "mma.sync.aligned.m16n8k8.row.col.f32.tf32.tf32.f32 "
        "{%0,%1,%2,%3}, {%4,%5,%6,%7}, {%8,%9}, {%0,%1,%2,%3};"
        : "+f"(c[0]), "+f"(c[1]), "+f"(c[2]), "+f"(c[3])
        : "r"(a0), "r"(a1), "r"(a2), "r"(a3), "r"(b0), "r"(b1));
}

// ---------------- K0: zero the kv/ksum accumulators ------------------------
__global__ void zero_acc_kernel() {
    int i = blockIdx.x * blockDim.x + threadIdx.x;
    const int NKV = BATCH * NHEADS * DHEAD * DHEAD;   // 262144
    const int NKS = BATCH * NHEADS * DHEAD;           // 4096
    if (i < NKV) g_kv[i] = 0.0f;
    if (i < NKS) g_ksum[i] = 0.0f;
}

// ============================================================================
// tf32 tensor-core GEMM: C[M,N] = A[M,K] * B[K,N], A,B row-major fp32.
// Block tile 128x128, BK=16, 256 threads = 8 warps (warp grid 4x2, warp tile
// 32x64, mma grid 2x8 of m16n8k8).
// EPI = 0: qkv epilogue (elu1 + contact scaling, scatter into g_q/g_k/g_v)
// EPI = 1: out epilogue (bias add, write to y)
// ============================================================================
template <int KDIM, int EPI>
__global__ __launch_bounds__(256) void gemm_tf32_kernel(
    const float* __restrict__ A,      // [M, KDIM]
    const float* __restrict__ Bbase,  // [BATCH][KDIM][NPIX]
    const float* __restrict__ cm,     // contact map (EPI==0)
    const float* __restrict__ csp,    // contact scale (EPI==0)
    const float* __restrict__ bout,   // bias (EPI==1)
    float* __restrict__ y)            // output (EPI==1)
{
    const int b     = blockIdx.z;
    const int mBase = blockIdx.y * 128;
    const int nBase = blockIdx.x * 128;
    const float* Bm = Bbase + (size_t)b * KDIM * NPIX;

    __shared__ uint32_t As[16][132];   // [k][m], +4 pad
    __shared__ uint32_t Bs[16][132];   // [k][n], +4 pad

    const int tid  = threadIdx.x;
    const int wid  = tid >> 5;
    const int lane = tid & 31;
    const int wm   = wid & 3;          // 0..3, 32-row slab
    const int wn   = wid >> 2;         // 0..1, 64-col slab
    const int lr   = lane >> 2;        // 0..7
    const int lc   = lane & 3;         // 0..3

    float acc[2][8][4];
    #pragma unroll
    for (int mt = 0; mt < 2; mt++)
        #pragma unroll
        for (int nt = 0; nt < 8; nt++)
            #pragma unroll
            for (int i = 0; i < 4; i++) acc[mt][nt][i] = 0.0f;

    // load indices
    const int aRow = tid >> 2;          // 0..63 (two rounds: +64)
    const int aK4  = (tid & 3) * 4;     // 0,4,8,12
    const int bK   = tid >> 5;          // 0..7 (two rounds: +8)
    const int bN4  = (tid & 31) * 4;    // 0..124

    for (int k0 = 0; k0 < KDIM; k0 += 16) {
        // ---- stage A tile (128x16) ----
        #pragma unroll
        for (int rr = 0; rr < 2; rr++) {
            int row = aRow + rr * 64;
            float4 av = *(const float4*)&A[(size_t)(mBase + row) * KDIM + k0 + aK4];
            As[aK4 + 0][row] = f2tf32(av.x);
            As[aK4 + 1][row] = f2tf32(av.y);
            As[aK4 + 2][row] = f2tf32(av.z);
            As[aK4 + 3][row] = f2tf32(av.w);
        }
        // ---- stage B tile (16x128) ----
        #pragma unroll
        for (int rr = 0; rr < 2; rr++) {
            int krow = bK + rr * 8;
            float4 bv = *(const float4*)&Bm[(size_t)(k0 + krow) * NPIX + nBase + bN4];
            uint4 pv;
            pv.x = f2tf32(bv.x); pv.y = f2tf32(bv.y);
            pv.z = f2tf32(bv.z); pv.w = f2tf32(bv.w);
            *(uint4*)&Bs[krow][bN4] = pv;
        }
        __syncthreads();

        #pragma unroll
        for (int kk = 0; kk < 16; kk += 8) {
            // A fragments: 2 m-tiles
            uint32_t af[2][4];
            #pragma unroll
            for (int mt = 0; mt < 2; mt++) {
                int m0 = wm * 32 + mt * 16 + lr;
                af[mt][0] = As[kk + lc][m0];
                af[mt][1] = As[kk + lc][m0 + 8];
                af[mt][2] = As[kk + lc + 4][m0];
                af[mt][3] = As[kk + lc + 4][m0 + 8];
            }
            // B fragments: 8 n-tiles
            uint32_t bf[8][2];
            #pragma unroll
            for (int nt = 0; nt < 8; nt++) {
                int n0 = wn * 64 + nt * 8 + lr;
                bf[nt][0] = Bs[kk + lc][n0];
                bf[nt][1] = Bs[kk + lc + 4][n0];
            }
            #pragma unroll
            for (int mt = 0; mt < 2; mt++)
                #pragma unroll
                for (int nt = 0; nt < 8; nt++)
                    mma_tf32(acc[mt][nt], af[mt][0], af[mt][1], af[mt][2], af[mt][3],
                             bf[nt][0], bf[nt][1]);
        }
        __syncthreads();
    }

    // ---------------- epilogue ----------------
    if (EPI == 0) {
        // qkv: mBase is a multiple of 128; group uniform per block.
        const int grp  = mBase >> 9;         // 0=q, 1=k, 2=v
        const int idx0 = mBase & 511;
        float* dst = (grp == 0) ? g_q : (grp == 1) ? g_k : g_v;
        float* base = dst + ((size_t)b * HID + idx0) * NPIX;
        const float cs = *csp;
        const float* cmb = cm + (size_t)b * NPIX;

        #pragma unroll
        for (int mt = 0; mt < 2; mt++) {
            #pragma unroll
            for (int half = 0; half < 2; half++) {
                int row = wm * 32 + mt * 16 + lr + half * 8;
                float* drow = base + (size_t)row * NPIX;
                #pragma unroll
                for (int nt = 0; nt < 8; nt++) {
                    int col = nBase + wn * 64 + nt * 8 + 2 * lc;
                    float v0 = acc[mt][nt][half * 2];
                    float v1 = acc[mt][nt][half * 2 + 1];
                    if (grp < 2) {
                        v0 = (v0 > 0.0f) ? (v0 + 1.0f) : __expf(v0);
                        v1 = (v1 > 0.0f) ? (v1 + 1.0f) : __expf(v1);
                    }
                    if (grp == 1) {
                        v0 *= (1.0f + cs * cmb[col]);
                        v1 *= (1.0f + cs * cmb[col + 1]);
                    }
                    drow[col]     = v0;
                    drow[col + 1] = v1;
                }
            }
        }
    } else {
        // out projection: bias + store
        #pragma unroll
        for (int mt = 0; mt < 2; mt++) {
            #pragma unroll
            for (int half = 0; half < 2; half++) {
                int row = mBase + wm * 32 + mt * 16 + lr + half * 8;
                const float bias = bout[row];
                float* drow = y + ((size_t)b * NDIM + row) * NPIX;
                #pragma unroll
                for (int nt = 0; nt < 8; nt++) {
                    int col = nBase + wn * 64 + nt * 8 + 2 * lc;
                    drow[col]     = acc[mt][nt][half * 2]     + bias;
                    drow[col + 1] = acc[mt][nt][half * 2 + 1] + bias;
                }
            }
        }
    }
}

// ---------------- K2: kv[d][e] += sum_n k[d][n]*v[e][n]; ksum[d] += sum k ---
__global__ __launch_bounds__(256) void kv_reduce_kernel()
{
    const int pair = blockIdx.y;              // b*8 + h
    const int b = pair >> 3, h = pair & 7;
    const int n0 = blockIdx.x * 512;
    const float* kp = g_k + ((size_t)b * HID + h * DHEAD) * NPIX;
    const float* vp = g_v + ((size_t)b * HID + h * DHEAD) * NPIX;

    __shared__ float ks[64][33];
    __shared__ float vs[64][33];

    const int tid = threadIdx.x;
    const int tx = tid & 15, ty = tid >> 4;

    float acc[4][4];
    #pragma unroll
    for (int i = 0; i < 4; i++)
        #pragma unroll
        for (int j = 0; j < 4; j++) acc[i][j] = 0.0f;
    float ksum = 0.0f;

    for (int kt = 0; kt < 512; kt += 32) {
        #pragma unroll
        for (int r = 0; r < 2; r++) {
            int li  = tid + r * 256;
            int row = li >> 3;
            int c4  = (li & 7) * 4;
            float4 kd = *(const float4*)&kp[(size_t)row * NPIX + n0 + kt + c4];
            ks[row][c4 + 0] = kd.x; ks[row][c4 + 1] = kd.y;
            ks[row][c4 + 2] = kd.z; ks[row][c4 + 3] = kd.w;
            float4 vd = *(const float4*)&vp[(size_t)row * NPIX + n0 + kt + c4];
            vs[row][c4 + 0] = vd.x; vs[row][c4 + 1] = vd.y;
            vs[row][c4 + 2] = vd.z; vs[row][c4 + 3] = vd.w;
        }
        __syncthreads();
        if (tid < 64) {
            #pragma unroll
            for (int c = 0; c < 32; c++) ksum += ks[tid][c];
        }
        #pragma unroll
        for (int c = 0; c < 32; c++) {
            float a[4], bb[4];
            #pragma unroll
            for (int i = 0; i < 4; i++) a[i] = ks[ty * 4 + i][c];
            #pragma unroll
            for (int j = 0; j < 4; j++) bb[j] = vs[tx * 4 + j][c];
            #pragma unroll
            for (int i = 0; i < 4; i++)
                #pragma unroll
                for (int j = 0; j < 4; j++) acc[i][j] += a[i] * bb[j];
        }
        __syncthreads();
    }

    float* kvp = g_kv + (size_t)pair * DHEAD * DHEAD;
    #pragma unroll
    for (int i = 0; i < 4; i++)
        #pragma unroll
        for (int j = 0; j < 4; j++)
            atomicAdd(&kvp[(ty * 4 + i) * DHEAD + tx * 4 + j], acc[i][j]);
    if (tid < 64) atomicAdd(&g_ksum[(size_t)pair * DHEAD + tid], ksum);
}

// ---------------- K3: out[h*64+e][n] = z * sum_d kv[d][e]*q[d][n] ----------
// Reworked: no qreg[64] cache -> low regs, high occupancy; q re-read from L1.
__global__ __launch_bounds__(256) void attn_out_kernel()
{
    const int pair = blockIdx.y;
    const int b = pair >> 3, h = pair & 7;
    const int n = blockIdx.x * 256 + threadIdx.x;
    const int tid = threadIdx.x;

    __shared__ float kvs[64][65];
    __shared__ float ksums[64];

    const float* kvp = g_kv + (size_t)pair * 4096;
    for (int i = tid; i < 4096; i += 256) kvs[i >> 6][i & 63] = kvp[i];
    if (tid < 64) ksums[tid] = g_ksum[(size_t)pair * 64 + tid];
    __syncthreads();

    const float* qp = g_q + ((size_t)b * HID + h * DHEAD) * NPIX + n;

    float denom = 1e-6f;
    #pragma unroll 16
    for (int d = 0; d < 64; d++)
        denom += qp[(size_t)d * NPIX] * ksums[d];
    const float z = 1.0f / denom;

    float* op = g_o + ((size_t)b * HID + h * DHEAD) * NPIX + n;
    #pragma unroll
    for (int et = 0; et < 4; et++) {
        float acc[16];
        #pragma unroll
        for (int e = 0; e < 16; e++) acc[e] = 0.0f;
        #pragma unroll 16
        for (int d = 0; d < 64; d++) {
            float qd = qp[(size_t)d * NPIX];
            #pragma unroll
            for (int e = 0; e < 16; e++) acc[e] += kvs[d][et * 16 + e] * qd;
        }
        #pragma unroll
        for (int e = 0; e < 16; e++)
            op[(size_t)(et * 16 + e) * NPIX] = acc[e] * z;
    }
}

// ---------------- launch ----------------------------------------------------
extern "C" void kernel_launch(void* const* d_in, const int* in_sizes, int n_in,
                              void* d_out, int out_size)
{
    const float* x    = (const float*)d_in[0];  // [8,256,64,64]
    const float* cm   = (const float*)d_in[1];  // [8,1,64,64]
    const float* Wqkv = (const float*)d_in[2];  // [1536,256]
    const float* Wout = (const float*)d_in[3];  // [256,512]
    const float* bout = (const float*)d_in[4];  // [256]
    const float* cs   = (const float*)d_in[5];  // scalar
    float* y = (float*)d_out;                   // [8,256,64,64]

    // K0: zero accumulators
    zero_acc_kernel<<<(BATCH * NHEADS * DHEAD * DHEAD + 255) / 256, 256>>>();

    // K1: qkv projection (tf32 tensor) + elu1 + contact scaling
    {
        dim3 grid(NPIX / 128, M1 / 128, BATCH);   // 32 x 12 x 8
        gemm_tf32_kernel<NDIM, 0><<<grid, 256>>>(Wqkv, x, cm, cs, nullptr, nullptr);
    }

    // K2: kv outer-product reduction + ksum
    {
        dim3 grid(NPIX / 512, BATCH * NHEADS);    // 8 x 64
        kv_reduce_kernel<<<grid, 256>>>();
    }

    // K3: normalized attention output
    {
        dim3 grid(NPIX / 256, BATCH * NHEADS);    // 16 x 64
        attn_out_kernel<<<grid, 256>>>();
    }

    // K4: output projection (tf32 tensor) + bias
    {
        float* gobase;
        cudaGetSymbolAddress((void**)&gobase, g_o);
        dim3 grid(NPIX / 128, NDIM / 128, BATCH); // 32 x 2 x 8
        gemm_tf32_kernel<HID, 1><<<grid, 256>>>(Wout, gobase, nullptr, nullptr, bout, y);
    }
}

// round 3
// speedup vs baseline: 2.2281x; 1.1619x over previous
#include <cuda_runtime.h>
#include <cuda_bf16.h>
#include <cstdint>

#define BATCH 8
#define NDIM 256      // DIM
#define NHEADS 8
#define DHEAD 64
#define HID 512       // NHEADS*DHEAD
#define NPIX 4096     // 64*64
#define M1 1536       // 3*HID

// ---------------- scratch (device globals; no allocation allowed) ----------
__device__ float g_q[(size_t)BATCH * HID * NPIX];
__device__ float g_k[(size_t)BATCH * HID * NPIX];
__device__ float g_v[(size_t)BATCH * HID * NPIX];
__device__ float g_o[(size_t)BATCH * HID * NPIX];
__device__ float g_kv[(size_t)BATCH * NHEADS * DHEAD * DHEAD];   // [pair][d][e]
__device__ float g_ksum[(size_t)BATCH * NHEADS * DHEAD];

// ---------------- helpers ---------------------------------------------------
__device__ __forceinline__ uint32_t f2tf32(float x) {
    uint32_t r;
    asm("cvt.rna.tf32.f32 %0, %1;" : "=r"(r) : "f"(x));
    return r;
}

__device__ __forceinline__ void mma_tf32(float c[4],
                                         uint32_t a0, uint32_t a1, uint32_t a2, uint32_t a3,
                                         uint32_t b0, uint32_t b1) {
    asm volatile(
        "mma.sync.aligned.m16n8k8.row.col.f32.tf32.tf32.f32 "
        "{%0,%1,%2,%3}, {%4,%5,%6,%7}, {%8,%9}, {%0,%1,%2,%3};"
        : "+f"(c[0]), "+f"(c[1]), "+f"(c[2]), "+f"(c[3])
        : "r"(a0), "r"(a1), "r"(a2), "r"(a3), "r"(b0), "r"(b1));
}

// ---------------- K0: zero the kv/ksum accumulators ------------------------
__global__ void zero_acc_kernel() {
    int i = blockIdx.x * blockDim.x + threadIdx.x;
    const int NKV = BATCH * NHEADS * DHEAD * DHEAD;   // 262144
    const int NKS = BATCH * NHEADS * DHEAD;           // 4096
    if (i < NKV) g_kv[i] = 0.0f;
    if (i < NKS) g_ksum[i] = 0.0f;
}

// ============================================================================
// tf32 tensor GEMM, double-buffered. C[M,N] = A[M,K]*B[K,N]. 128x128 tile,
// BK=16, 256 threads, warp tile 32x64 (mma grid 2x8 of m16n8k8).
// ============================================================================
template <int KDIM, int EPI>
__global__ __launch_bounds__(256) void gemm_tf32_kernel(
    const float* __restrict__ A,      // [M, KDIM]
    const float* __restrict__ Bbase,  // [BATCH][KDIM][NPIX]
    const float* __restrict__ cm,
    const float* __restrict__ csp,
    const float* __restrict__ bout,
    float* __restrict__ y)
{
    const int b     = blockIdx.z;
    const int mBase = blockIdx.y * 128;
    const int nBase = blockIdx.x * 128;
    const float* Bm = Bbase + (size_t)b * KDIM * NPIX;

    __shared__ uint32_t As[2][16][132];
    __shared__ uint32_t Bs[2][16][132];

    const int tid  = threadIdx.x;
    const int wid  = tid >> 5;
    const int lane = tid & 31;
    const int wm   = wid & 3;
    const int wn   = wid >> 2;
    const int lr   = lane >> 2;
    const int lc   = lane & 3;

    float acc[2][8][4];
    #pragma unroll
    for (int mt = 0; mt < 2; mt++)
        #pragma unroll
        for (int nt = 0; nt < 8; nt++)
            #pragma unroll
            for (int i = 0; i < 4; i++) acc[mt][nt][i] = 0.0f;

    const int aRow = tid >> 2;          // 0..63 (+64)
    const int aK4  = (tid & 3) * 4;     // 0,4,8,12
    const int bK   = tid >> 5;          // 0..7 (+8)
    const int bN4  = (tid & 31) * 4;    // 0..124

    const float* Ap0 = &A[(size_t)(mBase + aRow) * KDIM + aK4];
    const float* Ap1 = &A[(size_t)(mBase + aRow + 64) * KDIM + aK4];
    const float* Bp0 = &Bm[(size_t)bK * NPIX + nBase + bN4];
    const float* Bp1 = &Bm[(size_t)(bK + 8) * NPIX + nBase + bN4];

    float4 av0 = *(const float4*)Ap0;
    float4 av1 = *(const float4*)Ap1;
    float4 bv0 = *(const float4*)Bp0;
    float4 bv1 = *(const float4*)Bp1;

    // store buffer 0
    As[0][aK4 + 0][aRow] = f2tf32(av0.x); As[0][aK4 + 1][aRow] = f2tf32(av0.y);
    As[0][aK4 + 2][aRow] = f2tf32(av0.z); As[0][aK4 + 3][aRow] = f2tf32(av0.w);
    As[0][aK4 + 0][aRow + 64] = f2tf32(av1.x); As[0][aK4 + 1][aRow + 64] = f2tf32(av1.y);
    As[0][aK4 + 2][aRow + 64] = f2tf32(av1.z); As[0][aK4 + 3][aRow + 64] = f2tf32(av1.w);
    {
        uint4 p0, p1;
        p0.x = f2tf32(bv0.x); p0.y = f2tf32(bv0.y); p0.z = f2tf32(bv0.z); p0.w = f2tf32(bv0.w);
        p1.x = f2tf32(bv1.x); p1.y = f2tf32(bv1.y); p1.z = f2tf32(bv1.z); p1.w = f2tf32(bv1.w);
        *(uint4*)&Bs[0][bK][bN4]     = p0;
        *(uint4*)&Bs[0][bK + 8][bN4] = p1;
    }
    __syncthreads();

    const int nIter = KDIM / 16;
    for (int it = 0; it < nIter; it++) {
        const int cur = it & 1;
        if (it + 1 < nIter) {
            const int k0 = (it + 1) * 16;
            av0 = *(const float4*)(Ap0 + k0);
            av1 = *(const float4*)(Ap1 + k0);
            bv0 = *(const float4*)(Bp0 + (size_t)k0 * NPIX);
            bv1 = *(const float4*)(Bp1 + (size_t)k0 * NPIX);
        }
        #pragma unroll
        for (int kk = 0; kk < 16; kk += 8) {
            uint32_t af[2][4];
            #pragma unroll
            for (int mt = 0; mt < 2; mt++) {
                int m0 = wm * 32 + mt * 16 + lr;
                af[mt][0] = As[cur][kk + lc][m0];
                af[mt][1] = As[cur][kk + lc][m0 + 8];
                af[mt][2] = As[cur][kk + lc + 4][m0];
                af[mt][3] = As[cur][kk + lc + 4][m0 + 8];
            }
            #pragma unroll
            for (int nt = 0; nt < 8; nt++) {
                int n0 = wn * 64 + nt * 8 + lr;
                uint32_t b0 = Bs[cur][kk + lc][n0];
                uint32_t b1 = Bs[cur][kk + lc + 4][n0];
                #pragma unroll
                for (int mt = 0; mt < 2; mt++)
                    mma_tf32(acc[mt][nt], af[mt][0], af[mt][1], af[mt][2], af[mt][3],
                             b0, b1);
            }
        }
        if (it + 1 < nIter) {
            const int nb = cur ^ 1;
            As[nb][aK4 + 0][aRow] = f2tf32(av0.x); As[nb][aK4 + 1][aRow] = f2tf32(av0.y);
            As[nb][aK4 + 2][aRow] = f2tf32(av0.z); As[nb][aK4 + 3][aRow] = f2tf32(av0.w);
            As[nb][aK4 + 0][aRow + 64] = f2tf32(av1.x); As[nb][aK4 + 1][aRow + 64] = f2tf32(av1.y);
            As[nb][aK4 + 2][aRow + 64] = f2tf32(av1.z); As[nb][aK4 + 3][aRow + 64] = f2tf32(av1.w);
            uint4 p0, p1;
            p0.x = f2tf32(bv0.x); p0.y = f2tf32(bv0.y); p0.z = f2tf32(bv0.z); p0.w = f2tf32(bv0.w);
            p1.x = f2tf32(bv1.x); p1.y = f2tf32(bv1.y); p1.z = f2tf32(bv1.z); p1.w = f2tf32(bv1.w);
            *(uint4*)&Bs[nb][bK][bN4]     = p0;
            *(uint4*)&Bs[nb][bK + 8][bN4] = p1;
        }
        __syncthreads();
    }

    // ---------------- epilogue ----------------
    if (EPI == 0) {
        const int grp  = mBase >> 9;         // 0=q, 1=k, 2=v
        const int idx0 = mBase & 511;
        float* dst = (grp == 0) ? g_q : (grp == 1) ? g_k : g_v;
        float* base = dst + ((size_t)b * HID + idx0) * NPIX;
        const float cs = *csp;
        const float* cmb = cm + (size_t)b * NPIX;

        #pragma unroll
        for (int mt = 0; mt < 2; mt++) {
            #pragma unroll
            for (int half = 0; half < 2; half++) {
                int row = wm * 32 + mt * 16 + lr + half * 8;
                float* drow = base + (size_t)row * NPIX;
                #pragma unroll
                for (int nt = 0; nt < 8; nt++) {
                    int col = nBase + wn * 64 + nt * 8 + 2 * lc;
                    float v0 = acc[mt][nt][half * 2];
                    float v1 = acc[mt][nt][half * 2 + 1];
                    if (grp < 2) {
                        v0 = (v0 > 0.0f) ? (v0 + 1.0f) : __expf(v0);
                        v1 = (v1 > 0.0f) ? (v1 + 1.0f) : __expf(v1);
                    }
                    if (grp == 1) {
                        v0 *= (1.0f + cs * cmb[col]);
                        v1 *= (1.0f + cs * cmb[col + 1]);
                    }
                    drow[col]     = v0;
                    drow[col + 1] = v1;
                }
            }
        }
    } else {
        #pragma unroll
        for (int mt = 0; mt < 2; mt++) {
            #pragma unroll
            for (int half = 0; half < 2; half++) {
                int row = mBase + wm * 32 + mt * 16 + lr + half * 8;
                const float bias = bout[row];
                float* drow = y + ((size_t)b * NDIM + row) * NPIX;
                #pragma unroll
                for (int nt = 0; nt < 8; nt++) {
                    int col = nBase + wn * 64 + nt * 8 + 2 * lc;
                    drow[col]     = acc[mt][nt][half * 2]     + bias;
                    drow[col + 1] = acc[mt][nt][half * 2 + 1] + bias;
                }
            }
        }
    }
}

// ============================================================================
// K2 (tensor): kv[d][e] = sum_n k[d][n] * v[e][n]; ksum[d] = sum_n k[d][n].
// A = k (m=d, k-dim=n, row-major, natural); B = v (col=e, k-dim=n, natural).
// Block: one (pair, 1024-n chunk). 256 threads, warp grid 4(d) x 2(e).
// ============================================================================
__global__ __launch_bounds__(256) void kv_tc_kernel()
{
    const int pair = blockIdx.y;
    const int b = pair >> 3, h = pair & 7;
    const int n0 = blockIdx.x * 1024;
    const float* kp = g_k + ((size_t)b * HID + h * DHEAD) * NPIX;
    const float* vp = g_v + ((size_t)b * HID + h * DHEAD) * NPIX;

    __shared__ uint32_t ks[64][68];   // [d][n] ; 68 % 32 == 4 -> conflict-free frags
    __shared__ uint32_t vs[64][68];   // [e][n]

    const int tid  = threadIdx.x;
    const int wid  = tid >> 5;
    const int lane = tid & 31;
    const int lr   = lane >> 2;
    const int lc   = lane & 3;
    const int wm   = wid & 3;          // d slab of 16
    const int wn   = wid >> 2;         // e slab of 32

    float acc[4][4];
    #pragma unroll
    for (int nt = 0; nt < 4; nt++)
        #pragma unroll
        for (int i = 0; i < 4; i++) acc[nt][i] = 0.0f;
    float ksp[4] = {0.0f, 0.0f, 0.0f, 0.0f};

    for (int t = 0; t < 16; t++) {
        const int nb = n0 + t * 64;
        #pragma unroll
        for (int r = 0; r < 4; r++) {
            int li = tid + r * 256;
            int d  = li >> 4;             // 0..63
            int c4 = (li & 15) * 4;       // 0..60
            float4 kd = *(const float4*)&kp[(size_t)d * NPIX + nb + c4];
            ksp[r] += (kd.x + kd.y) + (kd.z + kd.w);
            uint4 kp4;
            kp4.x = f2tf32(kd.x); kp4.y = f2tf32(kd.y);
            kp4.z = f2tf32(kd.z); kp4.w = f2tf32(kd.w);
            *(uint4*)&ks[d][c4] = kp4;
            float4 vd = *(const float4*)&vp[(size_t)d * NPIX + nb + c4];
            uint4 vp4;
            vp4.x = f2tf32(vd.x); vp4.y = f2tf32(vd.y);
            vp4.z = f2tf32(vd.z); vp4.w = f2tf32(vd.w);
            *(uint4*)&vs[d][c4] = vp4;
        }
        __syncthreads();
        #pragma unroll
        for (int kk = 0; kk < 64; kk += 8) {
            const int m0 = wm * 16 + lr;
            uint32_t a0 = ks[m0][kk + lc];
            uint32_t a1 = ks[m0 + 8][kk + lc];
            uint32_t a2 = ks[m0][kk + lc + 4];
            uint32_t a3 = ks[m0 + 8][kk + lc + 4];
            #pragma unroll
            for (int nt = 0; nt < 4; nt++) {
                int e0 = wn * 32 + nt * 8 + lr;
                uint32_t b0 = vs[e0][kk + lc];
                uint32_t b1 = vs[e0][kk + lc + 4];
                mma_tf32(acc[nt], a0, a1, a2, a3, b0, b1);
            }
        }
        __syncthreads();
    }

    // ksum reduce: 16 consecutive tids share one d
    #pragma unroll
    for (int r = 0; r < 4; r++) {
        float s = ksp[r];
        s += __shfl_xor_sync(0xffffffffu, s, 8);
        s += __shfl_xor_sync(0xffffffffu, s, 4);
        s += __shfl_xor_sync(0xffffffffu, s, 2);
        s += __shfl_xor_sync(0xffffffffu, s, 1);
        if ((tid & 15) == 0)
            atomicAdd(&g_ksum[(size_t)pair * 64 + ((tid + r * 256) >> 4)], s);
    }

    float* kvp = g_kv + (size_t)pair * 4096;
    #pragma unroll
    for (int nt = 0; nt < 4; nt++) {
        int e = wn * 32 + nt * 8 + 2 * lc;
        int d = wm * 16 + lr;
        atomicAdd(&kvp[d * 64 + e],           acc[nt][0]);
        atomicAdd(&kvp[d * 64 + e + 1],       acc[nt][1]);
        atomicAdd(&kvp[(d + 8) * 64 + e],     acc[nt][2]);
        atomicAdd(&kvp[(d + 8) * 64 + e + 1], acc[nt][3]);
    }
}

// ============================================================================
// K3 (tensor): out[e][n] = z[n] * sum_d kv[d][e] * q[d][n].
// A = kv^T (staged transposed: kvt[e][d]); B = q (natural [d][n]).
// Block: (pair, 256-n tile). M=64, K=64, N=256. Dynamic smem.
// ============================================================================
__global__ __launch_bounds__(256) void attn_tc_kernel()
{
    extern __shared__ uint32_t dyn[];
    uint32_t* kvt   = dyn;                       // [64][68]
    uint32_t* qs    = dyn + 64 * 68;             // [64][264]  (264%32==8)
    float*    zs    = (float*)(qs + 64 * 264);   // [256]
    float*    ksums = zs + 256;                  // [64]

    const int pair = blockIdx.y;
    const int b = pair >> 3, h = pair & 7;
    const int nB  = blockIdx.x * 256;
    const int tid = threadIdx.x;
    const int wid = tid >> 5;
    const int lane = tid & 31;
    const int lr = lane >> 2;
    const int lc = lane & 3;

    // stage kv transposed
    const float* kvp = g_kv + (size_t)pair * 4096;
    #pragma unroll
    for (int r = 0; r < 16; r++) {
        int i = tid + r * 256;
        int d = i >> 6, e = i & 63;
        kvt[e * 68 + d] = f2tf32(kvp[i]);
    }
    if (tid < 64) ksums[tid] = g_ksum[(size_t)pair * 64 + tid];

    // stage q tile [64][256]
    const float* qp = g_q + ((size_t)b * HID + h * DHEAD) * NPIX + nB;
    #pragma unroll
    for (int r = 0; r < 16; r++) {
        int li = tid + r * 256;
        int d  = li >> 6;            // 0..63
        int c4 = (li & 63) * 4;      // 0..252
        float4 qv = *(const float4*)&qp[(size_t)d * NPIX + c4];
        qs[d * 264 + c4 + 0] = f2tf32(qv.x);
        qs[d * 264 + c4 + 1] = f2tf32(qv.y);
        qs[d * 264 + c4 + 2] = f2tf32(qv.z);
        qs[d * 264 + c4 + 3] = f2tf32(qv.w);
    }
    __syncthreads();

    // z per column
    {
        float denom = 1e-6f;
        #pragma unroll 16
        for (int d = 0; d < 64; d++)
            denom += __uint_as_float(qs[d * 264 + tid]) * ksums[d];
        zs[tid] = 1.0f / denom;
    }
    __syncthreads();

    // mma: warp n-slab of 32 (wid), full M=64 per warp (4 m-tiles)
    float acc[4][4][4];
    #pragma unroll
    for (int mt = 0; mt < 4; mt++)
        #pragma unroll
        for (int nt = 0; nt < 4; nt++)
            #pragma unroll
            for (int i = 0; i < 4; i++) acc[mt][nt][i] = 0.0f;

    #pragma unroll
    for (int kk = 0; kk < 64; kk += 8) {
        uint32_t af[4][4];
        #pragma unroll
        for (int mt = 0; mt < 4; mt++) {
            int m0 = mt * 16 + lr;
            af[mt][0] = kvt[m0 * 68 + kk + lc];
            af[mt][1] = kvt[(m0 + 8) * 68 + kk + lc];
            af[mt][2] = kvt[m0 * 68 + kk + lc + 4];
            af[mt][3] = kvt[(m0 + 8) * 68 + kk + lc + 4];
        }
        #pragma unroll
        for (int nt = 0; nt < 4; nt++) {
            int n0 = wid * 32 + nt * 8 + lr;
            uint32_t b0 = qs[(kk + lc) * 264 + n0];
            uint32_t b1 = qs[(kk + lc + 4) * 264 + n0];
            #pragma unroll
            for (int mt = 0; mt < 4; mt++)
                mma_tf32(acc[mt][nt], af[mt][0], af[mt][1], af[mt][2], af[mt][3],
                         b0, b1);
        }
    }

    // epilogue: scale by z, store to g_o
    float* ob = g_o + ((size_t)b * HID + h * DHEAD) * NPIX + nB;
    #pragma unroll
    for (int mt = 0; mt < 4; mt++) {
        #pragma unroll
        for (int half = 0; half < 2; half++) {
            int e = mt * 16 + lr + half * 8;
            float* orow = ob + (size_t)e * NPIX;
            #pragma unroll
            for (int nt = 0; nt < 4; nt++) {
                int nloc = wid * 32 + nt * 8 + 2 * lc;
                orow[nloc]     = acc[mt][nt][half * 2]     * zs[nloc];
                orow[nloc + 1] = acc[mt][nt][half * 2 + 1] * zs[nloc + 1];
            }
        }
    }
}

// ---------------- launch ----------------------------------------------------
extern "C" void kernel_launch(void* const* d_in, const int* in_sizes, int n_in,
                              void* d_out, int out_size)
{
    const float* x    = (const float*)d_in[0];
    const float* cm   = (const float*)d_in[1];
    const float* Wqkv = (const float*)d_in[2];
    const float* Wout = (const float*)d_in[3];
    const float* bout = (const float*)d_in[4];
    const float* cs   = (const float*)d_in[5];
    float* y = (float*)d_out;

    const int ATTN_SMEM = (64 * 68 + 64 * 264 + 256 + 64) * 4;   // 86272
    cudaFuncSetAttribute(attn_tc_kernel,
                         cudaFuncAttributeMaxDynamicSharedMemorySize, ATTN_SMEM);

    zero_acc_kernel<<<(BATCH * NHEADS * DHEAD * DHEAD + 255) / 256, 256>>>();

    {
        dim3 grid(NPIX / 128, M1 / 128, BATCH);   // 32 x 12 x 8
        gemm_tf32_kernel<NDIM, 0><<<grid, 256>>>(Wqkv, x, cm, cs, nullptr, nullptr);
    }
    {
        dim3 grid(NPIX / 1024, BATCH * NHEADS);   // 4 x 64
        kv_tc_kernel<<<grid, 256>>>();
    }
    {
        dim3 grid(NPIX / 256, BATCH * NHEADS);    // 16 x 64
        attn_tc_kernel<<<grid, 256, ATTN_SMEM>>>();
    }
    {
        float* gobase;
        cudaGetSymbolAddress((void**)&gobase, g_o);
        dim3 grid(NPIX / 128, NDIM / 128, BATCH); // 32 x 2 x 8
        gemm_tf32_kernel<HID, 1><<<grid, 256>>>(Wout, gobase, nullptr, nullptr, bout, y);
    }
}

// round 5
// speedup vs baseline: 2.8774x; 1.2914x over previous
#include <cuda_runtime.h>
#include <cuda_bf16.h>
#include <cstdint>

#define BATCH 8
#define NDIM 256      // DIM
#define NHEADS 8
#define DHEAD 64
#define HID 512       // NHEADS*DHEAD
#define NPIX 4096     // 64*64
#define M1 1536       // 3*HID

// ---------------- scratch (device globals; no allocation allowed) ----------
__device__ float g_q[(size_t)BATCH * HID * NPIX];
__device__ float g_k[(size_t)BATCH * HID * NPIX];
__device__ float g_v[(size_t)BATCH * HID * NPIX];
__device__ float g_o[(size_t)BATCH * HID * NPIX];
__device__ float g_kv[(size_t)BATCH * NHEADS * DHEAD * DHEAD];
__device__ float g_ksum[(size_t)BATCH * NHEADS * DHEAD];
__device__ float g_xt[(size_t)BATCH * NDIM * NPIX];     // tf32-rounded x
__device__ float g_wqkv[(size_t)M1 * NDIM];             // tf32-rounded Wqkv
__device__ float g_wout[(size_t)NDIM * HID];            // tf32-rounded Wout

// ---------------- helpers ---------------------------------------------------
__device__ __forceinline__ uint32_t f2tf32(float x) {
    uint32_t r;
    asm("cvt.rna.tf32.f32 %0, %1;" : "=r"(r) : "f"(x));
    return r;
}
__device__ __forceinline__ float f2tf32f(float x) {
    return __uint_as_float(f2tf32(x));
}

__device__ __forceinline__ void mma_tf32(float c[4],
                                         uint32_t a0, uint32_t a1, uint32_t a2, uint32_t a3,
                                         uint32_t b0, uint32_t b1) {
    asm volatile(
        "mma.sync.aligned.m16n8k8.row.col.f32.tf32.tf32.f32 "
        "{%0,%1,%2,%3}, {%4,%5,%6,%7}, {%8,%9}, {%0,%1,%2,%3};"
        : "+f"(c[0]), "+f"(c[1]), "+f"(c[2]), "+f"(c[3])
        : "r"(a0), "r"(a1), "r"(a2), "r"(a3), "r"(b0), "r"(b1));
}

__device__ __forceinline__ void cp16(uint32_t dst_smem, const void* src) {
    asm volatile("cp.async.cg.shared.global [%0], [%1], 16;"
                 :: "r"(dst_smem), "l"(src));
}

// ---------------- K-1: tf32 pre-conversion (vectorized) ---------------------
__global__ void convert_tf32_kernel(const float4* __restrict__ src,
                                    float4* __restrict__ dst, int n4) {
    int i = blockIdx.x * blockDim.x + threadIdx.x;
    if (i < n4) {
        float4 v = src[i];
        v.x = f2tf32f(v.x); v.y = f2tf32f(v.y);
        v.z = f2tf32f(v.z); v.w = f2tf32f(v.w);
        dst[i] = v;
    }
}

// ---------------- K0: zero the kv/ksum accumulators ------------------------
__global__ void zero_acc_kernel() {
    int i = blockIdx.x * blockDim.x + threadIdx.x;
    const int NKV = BATCH * NHEADS * DHEAD * DHEAD;
    const int NKS = BATCH * NHEADS * DHEAD;
    if (i < NKV) g_kv[i] = 0.0f;
    if (i < NKS) g_ksum[i] = 0.0f;
}

// ============================================================================
// tf32 tensor GEMM, cp.async 3-stage. C[M,N] = A[M,K]*B[K,N], inputs already
// tf32-rounded fp32 bits. 128x128 tile, BK=16, 256 threads, warp tile 32x64.
// Smem: A[m][20] (pad), B[k][136] (pad) -> conflict-free fragment LDS.
// ============================================================================
#define AST (128 * 20)
#define BST (16 * 136)
#define GEMM_SMEM ((3 * AST + 3 * BST) * 4)

template <int KDIM, int EPI>
__global__ __launch_bounds__(256) void gemm_tc_kernel(
    const float* __restrict__ A,      // [M, KDIM] tf32 bits
    const float* __restrict__ Bbase,  // [BATCH][KDIM][NPIX] tf32 bits
    const float* __restrict__ cm,
    const float* __restrict__ csp,
    const float* __restrict__ bout,
    float* __restrict__ y)
{
    extern __shared__ uint32_t dyn[];
    uint32_t* Asm = dyn;              // [3][128][20]
    uint32_t* Bsm = dyn + 3 * AST;    // [3][16][136]

    const int b     = blockIdx.z;
    const int mBase = blockIdx.y * 128;
    const int nBase = blockIdx.x * 128;
    const float* Bm = Bbase + (size_t)b * KDIM * NPIX;

    const int tid  = threadIdx.x;
    const int wid  = tid >> 5;
    const int lane = tid & 31;
    const int wm   = wid & 3;
    const int wn   = wid >> 2;
    const int lr   = lane >> 2;
    const int lc   = lane & 3;

    // cp.async thread mapping
    const int aRow = tid >> 2;          // 0..63 (+64)
    const int aSeg = (tid & 3) * 4;     // word seg within 16-k row
    const int bRow = tid >> 5;          // 0..7 (+8)
    const int bSeg = (tid & 31) * 4;    // 0..124

    const uint32_t smemBase = (uint32_t)__cvta_generic_to_shared(dyn);
    const float* aSrc0 = &A[(size_t)(mBase + aRow) * KDIM + aSeg];
    const float* aSrc1 = &A[(size_t)(mBase + aRow + 64) * KDIM + aSeg];
    const float* bSrc0 = &Bm[(size_t)bRow * NPIX + nBase + bSeg];
    const float* bSrc1 = &Bm[(size_t)(bRow + 8) * NPIX + nBase + bSeg];
    const uint32_t aDst0 = smemBase + (aRow * 20 + aSeg) * 4;
    const uint32_t aDst1 = smemBase + ((aRow + 64) * 20 + aSeg) * 4;
    const uint32_t bDst0 = smemBase + (3 * AST + bRow * 136 + bSeg) * 4;
    const uint32_t bDst1 = smemBase + (3 * AST + (bRow + 8) * 136 + bSeg) * 4;

    const int nIter = KDIM / 16;

    // prologue: stages 0,1
    #pragma unroll
    for (int s = 0; s < 2; s++) {
        const int k0 = s * 16;
        cp16(aDst0 + s * AST * 4, aSrc0 + k0);
        cp16(aDst1 + s * AST * 4, aSrc1 + k0);
        cp16(bDst0 + s * BST * 4, bSrc0 + (size_t)k0 * NPIX);
        cp16(bDst1 + s * BST * 4, bSrc1 + (size_t)k0 * NPIX);
        asm volatile("cp.async.commit_group;");
    }

    float acc[2][8][4];
    #pragma unroll
    for (int mt = 0; mt < 2; mt++)
        #pragma unroll
        for (int nt = 0; nt < 8; nt++)
            #pragma unroll
            for (int i = 0; i < 4; i++) acc[mt][nt][i] = 0.0f;

    int cur = 0;
    for (int it = 0; it < nIter; it++) {
        if (it == nIter - 1)
            asm volatile("cp.async.wait_group 0;");
        else
            asm volatile("cp.async.wait_group 1;");
        __syncthreads();

        const int pf = it + 2;
        if (pf < nIter) {
            const int s = pf % 3;
            const int k0 = pf * 16;
            cp16(aDst0 + s * AST * 4, aSrc0 + k0);
            cp16(aDst1 + s * AST * 4, aSrc1 + k0);
            cp16(bDst0 + s * BST * 4, bSrc0 + (size_t)k0 * NPIX);
            cp16(bDst1 + s * BST * 4, bSrc1 + (size_t)k0 * NPIX);
            asm volatile("cp.async.commit_group;");
        }

        const uint32_t* as = Asm + cur * AST;
        const uint32_t* bs = Bsm + cur * BST;
        #pragma unroll
        for (int kk = 0; kk < 16; kk += 8) {
            uint32_t af[2][4];
            #pragma unroll
            for (int mt = 0; mt < 2; mt++) {
                const int m0 = wm * 32 + mt * 16 + lr;
                af[mt][0] = as[m0 * 20 + kk + lc];
                af[mt][1] = as[(m0 + 8) * 20 + kk + lc];
                af[mt][2] = as[m0 * 20 + kk + lc + 4];
                af[mt][3] = as[(m0 + 8) * 20 + kk + lc + 4];
            }
            #pragma unroll
            for (int nt = 0; nt < 8; nt++) {
                const int n0 = wn * 64 + nt * 8 + lr;
                const uint32_t b0 = bs[(kk + lc) * 136 + n0];
                const uint32_t b1 = bs[(kk + lc + 4) * 136 + n0];
                #pragma unroll
                for (int mt = 0; mt < 2; mt++)
                    mma_tf32(acc[mt][nt], af[mt][0], af[mt][1], af[mt][2], af[mt][3],
                             b0, b1);
            }
        }
        cur++; if (cur == 3) cur = 0;
    }

    // ---------------- epilogue ----------------
    if (EPI == 0) {
        const int grp  = mBase >> 9;         // 0=q, 1=k, 2=v
        const int idx0 = mBase & 511;
        float* dst = (grp == 0) ? g_q : (grp == 1) ? g_k : g_v;
        float* base = dst + ((size_t)b * HID + idx0) * NPIX;
        const float cs = *csp;
        const float* cmb = cm + (size_t)b * NPIX;

        #pragma unroll
        for (int mt = 0; mt < 2; mt++) {
            #pragma unroll
            for (int half = 0; half < 2; half++) {
                const int row = wm * 32 + mt * 16 + lr + half * 8;
                float* drow = base + (size_t)row * NPIX;
                #pragma unroll
                for (int nt = 0; nt < 8; nt++) {
                    const int col = nBase + wn * 64 + nt * 8 + 2 * lc;
                    float v0 = acc[mt][nt][half * 2];
                    float v1 = acc[mt][nt][half * 2 + 1];
                    if (grp < 2) {
                        v0 = (v0 > 0.0f) ? (v0 + 1.0f) : __expf(v0);
                        v1 = (v1 > 0.0f) ? (v1 + 1.0f) : __expf(v1);
                    }
                    if (grp == 1) {
                        v0 *= (1.0f + cs * cmb[col]);
                        v1 *= (1.0f + cs * cmb[col + 1]);
                    }
                    // store tf32-rounded so downstream consumers use bits directly
                    drow[col]     = f2tf32f(v0);
                    drow[col + 1] = f2tf32f(v1);
                }
            }
        }
    } else {
        #pragma unroll
        for (int mt = 0; mt < 2; mt++) {
            #pragma unroll
            for (int half = 0; half < 2; half++) {
                const int row = mBase + wm * 32 + mt * 16 + lr + half * 8;
                const float bias = bout[row];
                float* drow = y + ((size_t)b * NDIM + row) * NPIX;
                #pragma unroll
                for (int nt = 0; nt < 8; nt++) {
                    const int col = nBase + wn * 64 + nt * 8 + 2 * lc;
                    drow[col]     = acc[mt][nt][half * 2]     + bias;
                    drow[col + 1] = acc[mt][nt][half * 2 + 1] + bias;
                }
            }
        }
    }
}

// ============================================================================
// K2 (tensor): kv[d][e] = sum_n k[d][n]*v[e][n]; ksum[d] = sum_n k[d][n].
// k,v already tf32 bits in gmem -> staging is bit copy.
// ============================================================================
__global__ __launch_bounds__(256) void kv_tc_kernel()
{
    const int pair = blockIdx.y;
    const int b = pair >> 3, h = pair & 7;
    const int n0 = blockIdx.x * 1024;
    const float* kp = g_k + ((size_t)b * HID + h * DHEAD) * NPIX;
    const float* vp = g_v + ((size_t)b * HID + h * DHEAD) * NPIX;

    __shared__ uint32_t ks[64][68];
    __shared__ uint32_t vs[64][68];

    const int tid  = threadIdx.x;
    const int wid  = tid >> 5;
    const int lane = tid & 31;
    const int lr   = lane >> 2;
    const int lc   = lane & 3;
    const int wm   = wid & 3;
    const int wn   = wid >> 2;

    float acc[4][4];
    #pragma unroll
    for (int nt = 0; nt < 4; nt++)
        #pragma unroll
        for (int i = 0; i < 4; i++) acc[nt][i] = 0.0f;
    float ksp[4] = {0.0f, 0.0f, 0.0f, 0.0f};

    for (int t = 0; t < 16; t++) {
        const int nb = n0 + t * 64;
        #pragma unroll
        for (int r = 0; r < 4; r++) {
            int li = tid + r * 256;
            int d  = li >> 4;
            int c4 = (li & 15) * 4;
            float4 kd = *(const float4*)&kp[(size_t)d * NPIX + nb + c4];
            ksp[r] += (kd.x + kd.y) + (kd.z + kd.w);
            *(uint4*)&ks[d][c4] = *(const uint4*)&kd;
            uint4 vd = *(const uint4*)&vp[(size_t)d * NPIX + nb + c4];
            *(uint4*)&vs[d][c4] = vd;
        }
        __syncthreads();
        #pragma unroll
        for (int kk = 0; kk < 64; kk += 8) {
            const int m0 = wm * 16 + lr;
            uint32_t a0 = ks[m0][kk + lc];
            uint32_t a1 = ks[m0 + 8][kk + lc];
            uint32_t a2 = ks[m0][kk + lc + 4];
            uint32_t a3 = ks[m0 + 8][kk + lc + 4];
            #pragma unroll
            for (int nt = 0; nt < 4; nt++) {
                int e0 = wn * 32 + nt * 8 + lr;
                uint32_t b0 = vs[e0][kk + lc];
                uint32_t b1 = vs[e0][kk + lc + 4];
                mma_tf32(acc[nt], a0, a1, a2, a3, b0, b1);
            }
        }
        __syncthreads();
    }

    #pragma unroll
    for (int r = 0; r < 4; r++) {
        float s = ksp[r];
        s += __shfl_xor_sync(0xffffffffu, s, 8);
        s += __shfl_xor_sync(0xffffffffu, s, 4);
        s += __shfl_xor_sync(0xffffffffu, s, 2);
        s += __shfl_xor_sync(0xffffffffu, s, 1);
        if ((tid & 15) == 0)
            atomicAdd(&g_ksum[(size_t)pair * 64 + ((tid + r * 256) >> 4)], s);
    }

    float* kvp = g_kv + (size_t)pair * 4096;
    #pragma unroll
    for (int nt = 0; nt < 4; nt++) {
        int e = wn * 32 + nt * 8 + 2 * lc;
        int d = wm * 16 + lr;
        atomicAdd(&kvp[d * 64 + e],           acc[nt][0]);
        atomicAdd(&kvp[d * 64 + e + 1],       acc[nt][1]);
        atomicAdd(&kvp[(d + 8) * 64 + e],     acc[nt][2]);
        atomicAdd(&kvp[(d + 8) * 64 + e + 1], acc[nt][3]);
    }
}

// ============================================================================
// K3 (tensor): out[e][n] = z[n] * sum_d kv[d][e]*q[d][n]. Writes g_o tf32.
// ============================================================================
__global__ __launch_bounds__(256) void attn_tc_kernel()
{
    extern __shared__ uint32_t dyn[];
    uint32_t* kvt   = dyn;                       // [64][68]
    uint32_t* qs    = dyn + 64 * 68;             // [64][264]
    float*    zs    = (float*)(qs + 64 * 264);   // [256]
    float*    ksums = zs + 256;                  // [64]

    const int pair = blockIdx.y;
    const int b = pair >> 3, h = pair & 7;
    const int nB  = blockIdx.x * 256;
    const int tid = threadIdx.x;
    const int wid = tid >> 5;
    const int lane = tid & 31;
    const int lr = lane >> 2;
    const int lc = lane & 3;

    const float* kvp = g_kv + (size_t)pair * 4096;
    #pragma unroll
    for (int r = 0; r < 16; r++) {
        int i = tid + r * 256;
        int d = i >> 6, e = i & 63;
        kvt[e * 68 + d] = f2tf32(kvp[i]);
    }
    if (tid < 64) ksums[tid] = g_ksum[(size_t)pair * 64 + tid];

    const float* qp = g_q + ((size_t)b * HID + h * DHEAD) * NPIX + nB;
    #pragma unroll
    for (int r = 0; r < 16; r++) {
        int li = tid + r * 256;
        int d  = li >> 6;
        int c4 = (li & 63) * 4;
        uint4 qv = *(const uint4*)&qp[(size_t)d * NPIX + c4];
        *(uint4*)&qs[d * 264 + c4] = qv;
    }
    __syncthreads();

    {
        float denom = 1e-6f;
        #pragma unroll 16
        for (int d = 0; d < 64; d++)
            denom += __uint_as_float(qs[d * 264 + tid]) * ksums[d];
        zs[tid] = 1.0f / denom;
    }
    __syncthreads();

    float acc[4][4][4];
    #pragma unroll
    for (int mt = 0; mt < 4; mt++)
        #pragma unroll
        for (int nt = 0; nt < 4; nt++)
            #pragma unroll
            for (int i = 0; i < 4; i++) acc[mt][nt][i] = 0.0f;

    #pragma unroll
    for (int kk = 0; kk < 64; kk += 8) {
        uint32_t af[4][4];
        #pragma unroll
        for (int mt = 0; mt < 4; mt++) {
            int m0 = mt * 16 + lr;
            af[mt][0] = kvt[m0 * 68 + kk + lc];
            af[mt][1] = kvt[(m0 + 8) * 68 + kk + lc];
            af[mt][2] = kvt[m0 * 68 + kk + lc + 4];
            af[mt][3] = kvt[(m0 + 8) * 68 + kk + lc + 4];
        }
        #pragma unroll
        for (int nt = 0; nt < 4; nt++) {
            int n0 = wid * 32 + nt * 8 + lr;
            uint32_t b0 = qs[(kk + lc) * 264 + n0];
            uint32_t b1 = qs[(kk + lc + 4) * 264 + n0];
            #pragma unroll
            for (int mt = 0; mt < 4; mt++)
                mma_tf32(acc[mt][nt], af[mt][0], af[mt][1], af[mt][2], af[mt][3],
                         b0, b1);
        }
    }

    float* ob = g_o + ((size_t)b * HID + h * DHEAD) * NPIX + nB;
    #pragma unroll
    for (int mt = 0; mt < 4; mt++) {
        #pragma unroll
        for (int half = 0; half < 2; half++) {
            int e = mt * 16 + lr + half * 8;
            float* orow = ob + (size_t)e * NPIX;
            #pragma unroll
            for (int nt = 0; nt < 4; nt++) {
                int nloc = wid * 32 + nt * 8 + 2 * lc;
                orow[nloc]     = f2tf32f(acc[mt][nt][half * 2]     * zs[nloc]);
                orow[nloc + 1] = f2tf32f(acc[mt][nt][half * 2 + 1] * zs[nloc + 1]);
            }
        }
    }
}

// ---------------- launch ----------------------------------------------------
extern "C" void kernel_launch(void* const* d_in, const int* in_sizes, int n_in,
                              void* d_out, int out_size)
{
    const float* x    = (const float*)d_in[0];
    const float* cm   = (const float*)d_in[1];
    const float* Wqkv = (const float*)d_in[2];
    const float* Wout = (const float*)d_in[3];
    const float* bout = (const float*)d_in[4];
    const float* cs   = (const float*)d_in[5];
    float* y = (float*)d_out;

    const int ATTN_SMEM = (64 * 68 + 64 * 264 + 256 + 64) * 4;   // 86272
    cudaFuncSetAttribute(attn_tc_kernel,
                         cudaFuncAttributeMaxDynamicSharedMemorySize, ATTN_SMEM);
    cudaFuncSetAttribute(gemm_tc_kernel<NDIM, 0>,
                         cudaFuncAttributeMaxDynamicSharedMemorySize, GEMM_SMEM);
    cudaFuncSetAttribute(gemm_tc_kernel<HID, 1>,
                         cudaFuncAttributeMaxDynamicSharedMemorySize, GEMM_SMEM);

    float *xt, *wqkvt, *woutt, *gobase;
    cudaGetSymbolAddress((void**)&xt, g_xt);
    cudaGetSymbolAddress((void**)&wqkvt, g_wqkv);
    cudaGetSymbolAddress((void**)&woutt, g_wout);
    cudaGetSymbolAddress((void**)&gobase, g_o);

    // pre-convert x, Wqkv, Wout to tf32 bits
    {
        int n4 = BATCH * NDIM * NPIX / 4;
        convert_tf32_kernel<<<(n4 + 255) / 256, 256>>>((const float4*)x, (float4*)xt, n4);
        n4 = M1 * NDIM / 4;
        convert_tf32_kernel<<<(n4 + 255) / 256, 256>>>((const float4*)Wqkv, (float4*)wqkvt, n4);
        n4 = NDIM * HID / 4;
        convert_tf32_kernel<<<(n4 + 255) / 256, 256>>>((const float4*)Wout, (float4*)woutt, n4);
    }

    zero_acc_kernel<<<(BATCH * NHEADS * DHEAD * DHEAD + 255) / 256, 256>>>();

    {
        dim3 grid(NPIX / 128, M1 / 128, BATCH);   // 32 x 12 x 8
        gemm_tc_kernel<NDIM, 0><<<grid, 256, GEMM_SMEM>>>(wqkvt, xt, cm, cs, nullptr, nullptr);
    }
    {
        dim3 grid(NPIX / 1024, BATCH * NHEADS);   // 4 x 64
        kv_tc_kernel<<<grid, 256>>>();
    }
    {
        dim3 grid(NPIX / 256, BATCH * NHEADS);    // 16 x 64
        attn_tc_kernel<<<grid, 256, ATTN_SMEM>>>();
    }
    {
        dim3 grid(NPIX / 128, NDIM / 128, BATCH); // 32 x 2 x 8
        gemm_tc_kernel<HID, 1><<<grid, 256, GEMM_SMEM>>>(woutt, gobase, nullptr, nullptr, bout, y);
    }
}

// round 6
// speedup vs baseline: 3.0176x; 1.0487x over previous
#include <cuda_runtime.h>
#include <cuda_bf16.h>
#include <cstdint>

#define BATCH 8
#define NDIM 256      // DIM
#define NHEADS 8
#define DHEAD 64
#define HID 512       // NHEADS*DHEAD
#define NPIX 4096     // 64*64
#define M1 1536       // 3*HID

// ---------------- scratch (device globals; no allocation allowed) ----------
__device__ float g_q[(size_t)BATCH * HID * NPIX];
__device__ float g_k[(size_t)BATCH * HID * NPIX];
__device__ float g_v[(size_t)BATCH * HID * NPIX];
__device__ float g_o[(size_t)BATCH * HID * NPIX];
__device__ float g_kv[(size_t)BATCH * NHEADS * DHEAD * DHEAD];
__device__ float g_ksum[(size_t)BATCH * NHEADS * DHEAD];
__device__ float g_wqkv[(size_t)M1 * NDIM];     // tf32 + k-interleaved Wqkv
__device__ float g_wout[(size_t)NDIM * HID];    // tf32 + k-interleaved Wout

// ---------------- helpers ---------------------------------------------------
__device__ __forceinline__ uint32_t f2tf32(float x) {
    uint32_t r;
    asm("cvt.rna.tf32.f32 %0, %1;" : "=r"(r) : "f"(x));
    return r;
}
__device__ __forceinline__ float f2tf32f(float x) {
    return __uint_as_float(f2tf32(x));
}

__device__ __forceinline__ void mma_tf32(float c[4],
                                         uint32_t a0, uint32_t a1, uint32_t a2, uint32_t a3,
                                         uint32_t b0, uint32_t b1) {
    asm volatile(
        "mma.sync.aligned.m16n8k8.row.col.f32.tf32.tf32.f32 "
        "{%0,%1,%2,%3}, {%4,%5,%6,%7}, {%8,%9}, {%0,%1,%2,%3};"
        : "+f"(c[0]), "+f"(c[1]), "+f"(c[2]), "+f"(c[3])
        : "r"(a0), "r"(a1), "r"(a2), "r"(a3), "r"(b0), "r"(b1));
}

__device__ __forceinline__ void cp16(uint32_t dst_smem, const void* src) {
    asm volatile("cp.async.cg.shared.global [%0], [%1], 16;"
                 :: "r"(dst_smem), "l"(src));
}

// ---------------- weight convert: tf32 round + k-pair interleave ------------
// dest col within each 8-group: k=0,4,1,5,2,6,3,7  (pairs (lc,lc+4) adjacent)
__global__ void convert_w_kernel(const float* __restrict__ src,
                                 float* __restrict__ dst, int total, int K) {
    int i = blockIdx.x * blockDim.x + threadIdx.x;
    if (i < total) {
        int k = i % K;
        int p = k & 7;
        int kd = (k & ~7) + ((p & 3) * 2 + (p >> 2));
        dst[i - k + kd] = f2tf32f(src[i]);
    }
}

// ---------------- K0: zero the kv/ksum accumulators ------------------------
__global__ void zero_acc_kernel() {
    int i = blockIdx.x * blockDim.x + threadIdx.x;
    const int NKV = BATCH * NHEADS * DHEAD * DHEAD;
    const int NKS = BATCH * NHEADS * DHEAD;
    if (i < NKV) g_kv[i] = 0.0f;
    if (i < NKS) g_ksum[i] = 0.0f;
}

// ============================================================================
// tf32 tensor GEMM, cp.async 3-stage. C = A*B. 128x128 tile, BK=16,
// 256 threads, warp grid 2(m)x4(n), warp tile 64x32 (mt=4, nt=4).
// A smem [128][24] (k-interleaved pairs -> ld.shared.v2, conflict-free);
// B smem [16][136].
// ============================================================================
#define ASTRIDE 24
#define AST (128 * ASTRIDE)
#define BST (16 * 136)
#define GEMM_SMEM ((3 * AST + 3 * BST) * 4)

template <int KDIM, int EPI>
__global__ __launch_bounds__(256) void gemm_tc_kernel(
    const float* __restrict__ A,      // [M, KDIM] tf32 bits, k-interleaved
    const float* __restrict__ Bbase,  // [BATCH][KDIM][NPIX] fp32 (HW-truncated)
    const float* __restrict__ cm,
    const float* __restrict__ csp,
    const float* __restrict__ bout,
    float* __restrict__ y)
{
    extern __shared__ uint32_t dyn[];
    uint32_t* Asm = dyn;              // [3][128][24]
    uint32_t* Bsm = dyn + 3 * AST;    // [3][16][136]

    const int b     = blockIdx.z;
    const int mBase = blockIdx.y * 128;
    const int nBase = blockIdx.x * 128;
    const float* Bm = Bbase + (size_t)b * KDIM * NPIX;

    const int tid  = threadIdx.x;
    const int wid  = tid >> 5;
    const int lane = tid & 31;
    const int wm   = wid >> 2;          // 0..1 : 64-row slab
    const int wn   = wid & 3;           // 0..3 : 32-col slab
    const int lr   = lane >> 2;
    const int lc   = lane & 3;

    const int aRow = tid >> 2;          // 0..63 (+64)
    const int aSeg = (tid & 3) * 4;
    const int bRow = tid >> 5;          // 0..7 (+8)
    const int bSeg = (tid & 31) * 4;

    const uint32_t smemBase = (uint32_t)__cvta_generic_to_shared(dyn);
    const float* aSrc0 = &A[(size_t)(mBase + aRow) * KDIM + aSeg];
    const float* aSrc1 = &A[(size_t)(mBase + aRow + 64) * KDIM + aSeg];
    const float* bSrc0 = &Bm[(size_t)bRow * NPIX + nBase + bSeg];
    const float* bSrc1 = &Bm[(size_t)(bRow + 8) * NPIX + nBase + bSeg];
    const uint32_t aDst0 = smemBase + (aRow * ASTRIDE + aSeg) * 4;
    const uint32_t aDst1 = smemBase + ((aRow + 64) * ASTRIDE + aSeg) * 4;
    const uint32_t bDst0 = smemBase + (3 * AST + bRow * 136 + bSeg) * 4;
    const uint32_t bDst1 = smemBase + (3 * AST + (bRow + 8) * 136 + bSeg) * 4;

    const int nIter = KDIM / 16;

    #pragma unroll
    for (int s = 0; s < 2; s++) {
        const int k0 = s * 16;
        cp16(aDst0 + s * AST * 4, aSrc0 + k0);
        cp16(aDst1 + s * AST * 4, aSrc1 + k0);
        cp16(bDst0 + s * BST * 4, bSrc0 + (size_t)k0 * NPIX);
        cp16(bDst1 + s * BST * 4, bSrc1 + (size_t)k0 * NPIX);
        asm volatile("cp.async.commit_group;");
    }

    float acc[4][4][4];
    #pragma unroll
    for (int mt = 0; mt < 4; mt++)
        #pragma unroll
        for (int nt = 0; nt < 4; nt++)
            #pragma unroll
            for (int i = 0; i < 4; i++) acc[mt][nt][i] = 0.0f;

    int cur = 0;
    for (int it = 0; it < nIter; it++) {
        if (it == nIter - 1)
            asm volatile("cp.async.wait_group 0;");
        else
            asm volatile("cp.async.wait_group 1;");
        __syncthreads();

        const int pf = it + 2;
        if (pf < nIter) {
            const int s = pf % 3;
            const int k0 = pf * 16;
            cp16(aDst0 + s * AST * 4, aSrc0 + k0);
            cp16(aDst1 + s * AST * 4, aSrc1 + k0);
            cp16(bDst0 + s * BST * 4, bSrc0 + (size_t)k0 * NPIX);
            cp16(bDst1 + s * BST * 4, bSrc1 + (size_t)k0 * NPIX);
            asm volatile("cp.async.commit_group;");
        }

        const uint32_t* as = Asm + cur * AST;
        const uint32_t* bs = Bsm + cur * BST;
        #pragma unroll
        for (int kk = 0; kk < 16; kk += 8) {
            // A fragments: v2 loads; interleave gives (k=lc, k=lc+4) adjacent
            uint32_t af[4][4];
            #pragma unroll
            for (int mt = 0; mt < 4; mt++) {
                const int m0 = wm * 64 + mt * 16 + lr;
                uint2 lo = *(const uint2*)&as[m0 * ASTRIDE + kk + 2 * lc];
                uint2 hi = *(const uint2*)&as[(m0 + 8) * ASTRIDE + kk + 2 * lc];
                af[mt][0] = lo.x; af[mt][1] = hi.x;
                af[mt][2] = lo.y; af[mt][3] = hi.y;
            }
            #pragma unroll
            for (int nt = 0; nt < 4; nt++) {
                const int n0 = wn * 32 + nt * 8 + lr;
                const uint32_t b0 = bs[(kk + lc) * 136 + n0];
                const uint32_t b1 = bs[(kk + lc + 4) * 136 + n0];
                #pragma unroll
                for (int mt = 0; mt < 4; mt++)
                    mma_tf32(acc[mt][nt], af[mt][0], af[mt][1], af[mt][2], af[mt][3],
                             b0, b1);
            }
        }
        cur++; if (cur == 3) cur = 0;
    }

    // ---------------- epilogue ----------------
    if (EPI == 0) {
        const int grp  = mBase >> 9;         // 0=q, 1=k, 2=v
        const int idx0 = mBase & 511;
        float* dst = (grp == 0) ? g_q : (grp == 1) ? g_k : g_v;
        float* base = dst + ((size_t)b * HID + idx0) * NPIX;
        const float cs = *csp;
        const float* cmb = cm + (size_t)b * NPIX;

        #pragma unroll
        for (int mt = 0; mt < 4; mt++) {
            #pragma unroll
            for (int half = 0; half < 2; half++) {
                const int row = wm * 64 + mt * 16 + lr + half * 8;
                float* drow = base + (size_t)row * NPIX;
                #pragma unroll
                for (int nt = 0; nt < 4; nt++) {
                    const int col = nBase + wn * 32 + nt * 8 + 2 * lc;
                    float v0 = acc[mt][nt][half * 2];
                    float v1 = acc[mt][nt][half * 2 + 1];
                    if (grp < 2) {
                        v0 = (v0 > 0.0f) ? (v0 + 1.0f) : __expf(v0);
                        v1 = (v1 > 0.0f) ? (v1 + 1.0f) : __expf(v1);
                    }
                    if (grp == 1) {
                        v0 *= (1.0f + cs * cmb[col]);
                        v1 *= (1.0f + cs * cmb[col + 1]);
                    }
                    drow[col]     = f2tf32f(v0);
                    drow[col + 1] = f2tf32f(v1);
                }
            }
        }
    } else {
        #pragma unroll
        for (int mt = 0; mt < 4; mt++) {
            #pragma unroll
            for (int half = 0; half < 2; half++) {
                const int row = mBase + wm * 64 + mt * 16 + lr + half * 8;
                const float bias = bout[row];
                float* drow = y + ((size_t)b * NDIM + row) * NPIX;
                #pragma unroll
                for (int nt = 0; nt < 4; nt++) {
                    const int col = nBase + wn * 32 + nt * 8 + 2 * lc;
                    drow[col]     = acc[mt][nt][half * 2]     + bias;
                    drow[col + 1] = acc[mt][nt][half * 2 + 1] + bias;
                }
            }
        }
    }
}

// ============================================================================
// K2 (tensor): kv[d][e] = sum_n k[d][n]*v[e][n]; ksum[d] = sum_n k[d][n].
// ============================================================================
__global__ __launch_bounds__(256) void kv_tc_kernel()
{
    const int pair = blockIdx.y;
    const int b = pair >> 3, h = pair & 7;
    const int n0 = blockIdx.x * 1024;
    const float* kp = g_k + ((size_t)b * HID + h * DHEAD) * NPIX;
    const float* vp = g_v + ((size_t)b * HID + h * DHEAD) * NPIX;

    __shared__ uint32_t ks[64][68];
    __shared__ uint32_t vs[64][68];

    const int tid  = threadIdx.x;
    const int wid  = tid >> 5;
    const int lane = tid & 31;
    const int lr   = lane >> 2;
    const int lc   = lane & 3;
    const int wm   = wid & 3;
    const int wn   = wid >> 2;

    float acc[4][4];
    #pragma unroll
    for (int nt = 0; nt < 4; nt++)
        #pragma unroll
        for (int i = 0; i < 4; i++) acc[nt][i] = 0.0f;
    float ksp[4] = {0.0f, 0.0f, 0.0f, 0.0f};

    for (int t = 0; t < 16; t++) {
        const int nb = n0 + t * 64;
        #pragma unroll
        for (int r = 0; r < 4; r++) {
            int li = tid + r * 256;
            int d  = li >> 4;
            int c4 = (li & 15) * 4;
            float4 kd = *(const float4*)&kp[(size_t)d * NPIX + nb + c4];
            ksp[r] += (kd.x + kd.y) + (kd.z + kd.w);
            *(uint4*)&ks[d][c4] = *(const uint4*)&kd;
            uint4 vd = *(const uint4*)&vp[(size_t)d * NPIX + nb + c4];
            *(uint4*)&vs[d][c4] = vd;
        }
        __syncthreads();
        #pragma unroll
        for (int kk = 0; kk < 64; kk += 8) {
            const int m0 = wm * 16 + lr;
            uint32_t a0 = ks[m0][kk + lc];
            uint32_t a1 = ks[m0 + 8][kk + lc];
            uint32_t a2 = ks[m0][kk + lc + 4];
            uint32_t a3 = ks[m0 + 8][kk + lc + 4];
            #pragma unroll
            for (int nt = 0; nt < 4; nt++) {
                int e0 = wn * 32 + nt * 8 + lr;
                uint32_t b0 = vs[e0][kk + lc];
                uint32_t b1 = vs[e0][kk + lc + 4];
                mma_tf32(acc[nt], a0, a1, a2, a3, b0, b1);
            }
        }
        __syncthreads();
    }

    #pragma unroll
    for (int r = 0; r < 4; r++) {
        float s = ksp[r];
        s += __shfl_xor_sync(0xffffffffu, s, 8);
        s += __shfl_xor_sync(0xffffffffu, s, 4);
        s += __shfl_xor_sync(0xffffffffu, s, 2);
        s += __shfl_xor_sync(0xffffffffu, s, 1);
        if ((tid & 15) == 0)
            atomicAdd(&g_ksum[(size_t)pair * 64 + ((tid + r * 256) >> 4)], s);
    }

    float* kvp = g_kv + (size_t)pair * 4096;
    #pragma unroll
    for (int nt = 0; nt < 4; nt++) {
        int e = wn * 32 + nt * 8 + 2 * lc;
        int d = wm * 16 + lr;
        atomicAdd(&kvp[d * 64 + e],           acc[nt][0]);
        atomicAdd(&kvp[d * 64 + e + 1],       acc[nt][1]);
        atomicAdd(&kvp[(d + 8) * 64 + e],     acc[nt][2]);
        atomicAdd(&kvp[(d + 8) * 64 + e + 1], acc[nt][3]);
    }
}

// ============================================================================
// K3 (tensor): out[e][n] = z[n] * sum_d kv[d][e]*q[d][n]. Writes g_o tf32.
// ============================================================================
__global__ __launch_bounds__(256) void attn_tc_kernel()
{
    extern __shared__ uint32_t dyn[];
    uint32_t* kvt   = dyn;                       // [64][68]
    uint32_t* qs    = dyn + 64 * 68;             // [64][264]
    float*    zs    = (float*)(qs + 64 * 264);   // [256]
    float*    ksums = zs + 256;                  // [64]

    const int pair = blockIdx.y;
    const int b = pair >> 3, h = pair & 7;
    const int nB  = blockIdx.x * 256;
    const int tid = threadIdx.x;
    const int wid = tid >> 5;
    const int lane = tid & 31;
    const int lr = lane >> 2;
    const int lc = lane & 3;

    const float* kvp = g_kv + (size_t)pair * 4096;
    #pragma unroll
    for (int r = 0; r < 16; r++) {
        int i = tid + r * 256;
        int d = i >> 6, e = i & 63;
        kvt[e * 68 + d] = f2tf32(kvp[i]);
    }
    if (tid < 64) ksums[tid] = g_ksum[(size_t)pair * 64 + tid];

    const float* qp = g_q + ((size_t)b * HID + h * DHEAD) * NPIX + nB;
    #pragma unroll
    for (int r = 0; r < 16; r++) {
        int li = tid + r * 256;
        int d  = li >> 6;
        int c4 = (li & 63) * 4;
        uint4 qv = *(const uint4*)&qp[(size_t)d * NPIX + c4];
        *(uint4*)&qs[d * 264 + c4] = qv;
    }
    __syncthreads();

    {
        float denom = 1e-6f;
        #pragma unroll 16
        for (int d = 0; d < 64; d++)
            denom += __uint_as_float(qs[d * 264 + tid]) * ksums[d];
        zs[tid] = 1.0f / denom;
    }
    __syncthreads();

    float acc[4][4][4];
    #pragma unroll
    for (int mt = 0; mt < 4; mt++)
        #pragma unroll
        for (int nt = 0; nt < 4; nt++)
            #pragma unroll
            for (int i = 0; i < 4; i++) acc[mt][nt][i] = 0.0f;

    #pragma unroll
    for (int kk = 0; kk < 64; kk += 8) {
        uint32_t af[4][4];
        #pragma unroll
        for (int mt = 0; mt < 4; mt++) {
            int m0 = mt * 16 + lr;
            af[mt][0] = kvt[m0 * 68 + kk + lc];
            af[mt][1] = kvt[(m0 + 8) * 68 + kk + lc];
            af[mt][2] = kvt[m0 * 68 + kk + lc + 4];
            af[mt][3] = kvt[(m0 + 8) * 68 + kk + lc + 4];
        }
        #pragma unroll
        for (int nt = 0; nt < 4; nt++) {
            int n0 = wid * 32 + nt * 8 + lr;
            uint32_t b0 = qs[(kk + lc) * 264 + n0];
            uint32_t b1 = qs[(kk + lc + 4) * 264 + n0];
            #pragma unroll
            for (int mt = 0; mt < 4; mt++)
                mma_tf32(acc[mt][nt], af[mt][0], af[mt][1], af[mt][2], af[mt][3],
                         b0, b1);
        }
    }

    float* ob = g_o + ((size_t)b * HID + h * DHEAD) * NPIX + nB;
    #pragma unroll
    for (int mt = 0; mt < 4; mt++) {
        #pragma unroll
        for (int half = 0; half < 2; half++) {
            int e = mt * 16 + lr + half * 8;
            float* orow = ob + (size_t)e * NPIX;
            #pragma unroll
            for (int nt = 0; nt < 4; nt++) {
                int nloc = wid * 32 + nt * 8 + 2 * lc;
                orow[nloc]     = f2tf32f(acc[mt][nt][half * 2]     * zs[nloc]);
                orow[nloc + 1] = f2tf32f(acc[mt][nt][half * 2 + 1] * zs[nloc + 1]);
            }
        }
    }
}

// ---------------- launch ----------------------------------------------------
extern "C" void kernel_launch(void* const* d_in, const int* in_sizes, int n_in,
                              void* d_out, int out_size)
{
    const float* x    = (const float*)d_in[0];
    const float* cm   = (const float*)d_in[1];
    const float* Wqkv = (const float*)d_in[2];
    const float* Wout = (const float*)d_in[3];
    const float* bout = (const float*)d_in[4];
    const float* cs   = (const float*)d_in[5];
    float* y = (float*)d_out;

    const int ATTN_SMEM = (64 * 68 + 64 * 264 + 256 + 64) * 4;   // 86272
    cudaFuncSetAttribute(attn_tc_kernel,
                         cudaFuncAttributeMaxDynamicSharedMemorySize, ATTN_SMEM);
    cudaFuncSetAttribute(gemm_tc_kernel<NDIM, 0>,
                         cudaFuncAttributeMaxDynamicSharedMemorySize, GEMM_SMEM);
    cudaFuncSetAttribute(gemm_tc_kernel<HID, 1>,
                         cudaFuncAttributeMaxDynamicSharedMemorySize, GEMM_SMEM);

    float *wqkvt, *woutt, *gobase;
    cudaGetSymbolAddress((void**)&wqkvt, g_wqkv);
    cudaGetSymbolAddress((void**)&woutt, g_wout);
    cudaGetSymbolAddress((void**)&gobase, g_o);

    // weight convert (tf32 round + k interleave); x stays raw (HW truncation)
    {
        int n = M1 * NDIM;
        convert_w_kernel<<<(n + 255) / 256, 256>>>(Wqkv, wqkvt, n, NDIM);
        n = NDIM * HID;
        convert_w_kernel<<<(n + 255) / 256, 256>>>(Wout, woutt, n, HID);
    }

    zero_acc_kernel<<<(BATCH * NHEADS * DHEAD * DHEAD + 255) / 256, 256>>>();

    {
        dim3 grid(NPIX / 128, M1 / 128, BATCH);   // 32 x 12 x 8
        gemm_tc_kernel<NDIM, 0><<<grid, 256, GEMM_SMEM>>>(wqkvt, x, cm, cs, nullptr, nullptr);
    }
    {
        dim3 grid(NPIX / 1024, BATCH * NHEADS);   // 4 x 64
        kv_tc_kernel<<<grid, 256>>>();
    }
    {
        dim3 grid(NPIX / 256, BATCH * NHEADS);    // 16 x 64
        attn_tc_kernel<<<grid, 256, ATTN_SMEM>>>();
    }
    {
        dim3 grid(NPIX / 128, NDIM / 128, BATCH); // 32 x 2 x 8
        gemm_tc_kernel<HID, 1><<<grid, 256, GEMM_SMEM>>>(woutt, gobase, nullptr, nullptr, bout, y);
    }
}